// round 4
// baseline (speedup 1.0000x reference)
#include <cuda_runtime.h>
#include <math.h>

// Fixed-shape problem: N=16384, D=8, pid in [0,2000), K=128, R=1
#define NMAX    16384
#define NPIDMAX 2048
#define KSEL    128
#define CPT     8       // condensation points per repulsion block
#define RT      256     // threads per block
#define MCAP    512     // per-CP shared buffer capacity
#define TRIG    256     // compact when cnt > TRIG at chunk end
#define NB      256     // histogram bins over d2 in [0,1]

// -------- device scratch (small, allocation-free) --------
__device__ unsigned long long g_best[NPIDMAX];   // per-pid packed (beta_bits<<32 | ~idx)
__device__ float  g_q[NMAX];
__device__ int    g_cplist[NPIDMAX];
__device__ int    g_cpcount;
__device__ double g_att;
__device__ double g_rep;
__device__ int    g_maskcnt;

__global__ void k_init() {
    int i = blockIdx.x * blockDim.x + threadIdx.x;
    if (i < NPIDMAX) g_best[i] = 0ULL;
    if (i == 0) { g_cpcount = 0; g_att = 0.0; g_rep = 0.0; g_maskcnt = 0; }
}

// q = arctanh(beta)^2 + 0.01 ; per-pid best (max beta, tie -> smallest index)
__global__ void k_bestq(const float* __restrict__ beta, const int* __restrict__ pid, int N) {
    int i = blockIdx.x * blockDim.x + threadIdx.x;
    if (i >= N) return;
    float b = beta[i];
    float t = atanhf(b);
    g_q[i] = t * t + 0.01f;
    int p = pid[i];
    if (p > 0 && p < NPIDMAX) {
        unsigned long long key =
            ((unsigned long long)__float_as_uint(b) << 32) |
            (unsigned long long)(0xFFFFFFFFu - (unsigned)i);
        atomicMax(&g_best[p], key);
    }
}

__global__ void k_compact() {
    int p = blockIdx.x * blockDim.x + threadIdx.x;
    if (p <= 0 || p >= NPIDMAX) return;
    unsigned long long key = g_best[p];
    if (key != 0ULL) {
        int idx = (int)(0xFFFFFFFFu - (unsigned)(key & 0xFFFFFFFFull));
        int pos = atomicAdd(&g_cpcount, 1);
        g_cplist[pos] = idx;
    }
}

// attraction: sum over masked hits of ||x_i - x_alpha||^2 * q_i * q_alpha
__global__ void k_attract(const float* __restrict__ x, const int* __restrict__ pid,
                          const int* __restrict__ recon, const float* __restrict__ pt,
                          const float* __restrict__ eta, int N) {
    int i = blockIdx.x * blockDim.x + threadIdx.x;
    float va = 0.0f; int m = 0;
    if (i < N) {
        int p = pid[i];
        if (p > 0 && pt[i] > 0.9f && recon[i] > 0 && fabsf(eta[i]) < 4.0f) {
            unsigned long long key = g_best[p];
            int a = (int)(0xFFFFFFFFu - (unsigned)(key & 0xFFFFFFFFull));
            const float4* xi = (const float4*)(x + (size_t)i * 8);
            const float4* xa = (const float4*)(x + (size_t)a * 8);
            float4 i0 = xi[0], i1 = xi[1], a0 = xa[0], a1 = xa[1];
            float d, d2 = 0.0f;
            d = i0.x - a0.x; d2 += d * d;
            d = i0.y - a0.y; d2 += d * d;
            d = i0.z - a0.z; d2 += d * d;
            d = i0.w - a0.w; d2 += d * d;
            d = i1.x - a1.x; d2 += d * d;
            d = i1.y - a1.y; d2 += d * d;
            d = i1.z - a1.z; d2 += d * d;
            d = i1.w - a1.w; d2 += d * d;
            va = d2 * g_q[i] * g_q[a];
            m = 1;
        }
    }
    #pragma unroll
    for (int o = 16; o; o >>= 1) {
        va += __shfl_down_sync(0xFFFFFFFFu, va, o);
        m  += __shfl_down_sync(0xFFFFFFFFu, m,  o);
    }
    if ((threadIdx.x & 31) == 0 && (m || va != 0.0f)) {
        atomicAdd(&g_att, (double)va);
        atomicAdd(&g_maskcnt, m);
    }
}

// ---- single-pass repulsion: streaming exact top-K per condensation point ----
__global__ void __launch_bounds__(RT) k_repulse(const float* __restrict__ x,
                                                const int* __restrict__ pid, int N) {
    __shared__ float    s_xc[CPT][8];
    __shared__ int      s_pidc[CPT];
    __shared__ int      s_cidx[CPT];
    __shared__ float    s_qc[CPT];
    __shared__ unsigned s_key[CPT][MCAP];   // d2 float bits (monotone, d2>=0)
    __shared__ float    s_w[CPT][MCAP];
    __shared__ int      s_cnt[CPT];
    __shared__ unsigned s_thr[CPT];
    __shared__ int      s_hist[NB];
    __shared__ int      s_csum[NB];
    __shared__ unsigned s_candk[MCAP];
    __shared__ float    s_candw[MCAP];
    __shared__ int      s_B, s_r, s_ccnt, s_newcnt;
    __shared__ float    s_red[RT / 32];

    int tid  = threadIdx.x;
    int ncp  = g_cpcount;
    int cbase = blockIdx.x * CPT;
    if (cbase >= ncp) return;
    int nact = min(CPT, ncp - cbase);

    if (tid < CPT) { s_cnt[tid] = 0; s_thr[tid] = 0xFFFFFFFFu; }
    if (tid < nact) {
        int c = g_cplist[cbase + tid];
        s_cidx[tid] = c;
        s_pidc[tid] = pid[c];
        s_qc[tid]   = g_q[c];
        #pragma unroll
        for (int d = 0; d < 8; d++) s_xc[tid][d] = x[(size_t)c * 8 + d];
    }
    __syncthreads();

    // chunked j-loop; N divisible by RT
    for (int j0 = 0; j0 < N; j0 += RT) {
        int j = j0 + tid;
        float4 v0 = *(const float4*)(x + (size_t)j * 8);
        float4 v1 = *(const float4*)(x + (size_t)j * 8 + 4);
        int   pj = pid[j];
        float qj = g_q[j];
        #pragma unroll
        for (int c = 0; c < CPT; c++) {
            if (c < nact) {
                float d, d2 = 0.0f;
                d = v0.x - s_xc[c][0]; d2 += d * d;
                d = v0.y - s_xc[c][1]; d2 += d * d;
                d = v0.z - s_xc[c][2]; d2 += d * d;
                d = v0.w - s_xc[c][3]; d2 += d * d;
                d = v1.x - s_xc[c][4]; d2 += d * d;
                d = v1.y - s_xc[c][5]; d2 += d * d;
                d = v1.z - s_xc[c][6]; d2 += d * d;
                d = v1.w - s_xc[c][7]; d2 += d * d;
                if (d2 <= 1.0f && j != s_cidx[c]) {
                    unsigned key = __float_as_uint(d2);
                    if (key < s_thr[c]) {
                        int pos = atomicAdd(&s_cnt[c], 1);   // pos < MCAP by invariant
                        s_key[c][pos] = key;
                        s_w[c][pos]   = (pj != s_pidc[c]) ? (1.0f - sqrtf(d2)) * qj : 0.0f;
                    }
                }
            }
        }
        __syncthreads();

        // compaction (uniform branches: all state in shared)
        for (int c = 0; c < nact; c++) {
            int n = min(s_cnt[c], MCAP);
            if (n > TRIG) {
                // 1) histogram of bins over buffer
                s_hist[tid] = 0;           // RT == NB
                __syncthreads();
                for (int e = tid; e < n; e += RT) {
                    float d2v = __uint_as_float(s_key[c][e]);
                    int b = min((int)(d2v * (float)NB), NB - 1);
                    atomicAdd(&s_hist[b], 1);
                }
                __syncthreads();
                // 2) inclusive scan
                int v = s_hist[tid];
                s_csum[tid] = v;
                __syncthreads();
                #pragma unroll
                for (int off = 1; off < NB; off <<= 1) {
                    int t = (tid >= off) ? s_csum[tid - off] : 0;
                    __syncthreads();
                    s_csum[tid] += t;
                    __syncthreads();
                }
                // 3) boundary bin B, residual r
                {
                    int cs = s_csum[tid];
                    int prev = tid ? s_csum[tid - 1] : 0;
                    if (cs >= KSEL && prev < KSEL) { s_B = tid; s_r = KSEL - prev; }
                }
                if (tid == 0) { s_ccnt = 0; s_newcnt = 0; }
                __syncthreads();
                int B = s_B, r = s_r;
                // 4) stage own entries into regs; gather boundary candidates
                unsigned myk[2]; float myw[2]; int myb[2]; int ne = 0;
                for (int e = tid; e < n; e += RT) {
                    unsigned ke = s_key[c][e]; float we = s_w[c][e];
                    float d2v = __uint_as_float(ke);
                    int b = min((int)(d2v * (float)NB), NB - 1);
                    myk[ne] = ke; myw[ne] = we; myb[ne] = b; ne++;
                    if (b == B) {
                        int p = atomicAdd(&s_ccnt, 1);
                        s_candk[p] = ke; s_candw[p] = we;
                    }
                }
                __syncthreads();
                // 5) rewrite keepers (bin < B)
                for (int t = 0; t < ne; t++) {
                    if (myb[t] < B) {
                        int pos = atomicAdd(&s_newcnt, 1);
                        s_key[c][pos] = myk[t]; s_w[c][pos] = myw[t];
                    }
                }
                __syncthreads();
                // 6) boundary mini-rank: append r smallest; set threshold
                int m = s_ccnt;
                for (int t = tid; t < m; t += RT) {
                    unsigned ke = s_candk[t];
                    int rank = 0;
                    for (int k = 0; k < m; k++) rank += (s_candk[k] < ke);
                    if (rank < r) {
                        int pos = atomicAdd(&s_newcnt, 1);
                        s_key[c][pos] = ke; s_w[c][pos] = s_candw[t];
                    }
                    if (rank == r - 1) s_thr[c] = ke;
                }
                __syncthreads();
                if (tid == 0) s_cnt[c] = s_newcnt;
                __syncthreads();
            }
        }
    }

    // ---- final exact selection + accumulate ----
    for (int c = 0; c < nact; c++) {
        int n = min(s_cnt[c], MCAP);
        float part = 0.0f;
        if (n > KSEL) {
            s_hist[tid] = 0;
            __syncthreads();
            for (int e = tid; e < n; e += RT) {
                float d2v = __uint_as_float(s_key[c][e]);
                int b = min((int)(d2v * (float)NB), NB - 1);
                atomicAdd(&s_hist[b], 1);
            }
            __syncthreads();
            int v = s_hist[tid];
            s_csum[tid] = v;
            __syncthreads();
            #pragma unroll
            for (int off = 1; off < NB; off <<= 1) {
                int t = (tid >= off) ? s_csum[tid - off] : 0;
                __syncthreads();
                s_csum[tid] += t;
                __syncthreads();
            }
            {
                int cs = s_csum[tid];
                int prev = tid ? s_csum[tid - 1] : 0;
                if (cs >= KSEL && prev < KSEL) { s_B = tid; s_r = KSEL - prev; }
            }
            if (tid == 0) s_ccnt = 0;
            __syncthreads();
            int B = s_B, r = s_r;
            for (int e = tid; e < n; e += RT) {
                unsigned ke = s_key[c][e]; float we = s_w[c][e];
                float d2v = __uint_as_float(ke);
                int b = min((int)(d2v * (float)NB), NB - 1);
                if (b < B) part += we;
                else if (b == B) {
                    int p = atomicAdd(&s_ccnt, 1);
                    s_candk[p] = ke; s_candw[p] = we;
                }
            }
            __syncthreads();
            int m = s_ccnt;
            for (int t = tid; t < m; t += RT) {
                unsigned ke = s_candk[t];
                int rank = 0;
                for (int k = 0; k < m; k++) rank += (s_candk[k] < ke);
                if (rank < r) part += s_candw[t];
            }
        } else {
            for (int e = tid; e < n; e += RT) part += s_w[c][e];
        }
        // block reduction
        #pragma unroll
        for (int o = 16; o; o >>= 1) part += __shfl_down_sync(0xFFFFFFFFu, part, o);
        if ((tid & 31) == 0) s_red[tid >> 5] = part;
        __syncthreads();
        if (tid == 0) {
            float tot = 0.0f;
            #pragma unroll
            for (int w = 0; w < RT / 32; w++) tot += s_red[w];
            atomicAdd(&g_rep, (double)(tot * s_qc[c]));
        }
        __syncthreads();
    }
}

__global__ void k_final(float* out, int N) {
    if (blockIdx.x == 0 && threadIdx.x == 0) {
        int mc = g_maskcnt;
        out[0] = (float)(mc > 0 ? g_att / (double)mc : 0.0);
        out[1] = (float)(g_rep / (double)N);
        out[2] = 0.0f;
        out[3] = 0.0f;
    }
}

extern "C" void kernel_launch(void* const* d_in, const int* in_sizes, int n_in,
                              void* d_out, int out_size) {
    const float* beta  = (const float*)d_in[0];
    const float* x     = (const float*)d_in[1];
    const int*   pid   = (const int*)d_in[2];
    const int*   recon = (const int*)d_in[3];
    const float* pt    = (const float*)d_in[4];
    const float* eta   = (const float*)d_in[5];
    float* out = (float*)d_out;
    int N = in_sizes[0];

    k_init<<<(NPIDMAX + 255) / 256, 256>>>();
    k_bestq<<<(N + 255) / 256, 256>>>(beta, pid, N);
    k_compact<<<(NPIDMAX + 255) / 256, 256>>>();
    k_attract<<<(N + 127) / 128, 128>>>(x, pid, recon, pt, eta, N);
    int ngrp = (NPIDMAX + CPT - 1) / CPT;   // 256 blocks; inactive exit on g_cpcount
    k_repulse<<<ngrp, RT>>>(x, pid, N);
    k_final<<<1, 32>>>(out, N);
}

// round 5
// speedup vs baseline: 1.8424x; 1.8424x over previous
#include <cuda_runtime.h>
#include <math.h>

// Fixed-shape problem: N=16384, D=8, pid in [0,2000), K=128, R=1
#define NMAX    16384
#define NPIDMAX 2048
#define KSEL2   129     // top-(K+1) including self (self weight = 0)
#define CPT     8       // condensation points per repulsion block
#define RT      256     // threads per block
#define NB      256     // histogram bins over d2 in [0,1]
#define BCAP    192     // boundary-bin candidate capacity per CP

// -------- device scratch (small, allocation-free) --------
__device__ unsigned long long g_best[NPIDMAX];   // per-pid packed (beta_bits<<32 | ~idx)
__device__ float  g_q[NMAX];
__device__ float  g_n2[NMAX];                    // |x_j|^2
__device__ int    g_cplist[NPIDMAX];
__device__ int    g_cpcount;
__device__ double g_att;
__device__ double g_rep;
__device__ int    g_maskcnt;

__global__ void k_init() {
    int i = blockIdx.x * blockDim.x + threadIdx.x;
    if (i < NPIDMAX) g_best[i] = 0ULL;
    if (i == 0) { g_cpcount = 0; g_att = 0.0; g_rep = 0.0; g_maskcnt = 0; }
}

// q = arctanh(beta)^2 + 0.01 ; |x|^2 ; per-pid best (max beta, tie -> smallest idx)
__global__ void k_bestq(const float* __restrict__ beta, const int* __restrict__ pid,
                        const float* __restrict__ x, int N) {
    int i = blockIdx.x * blockDim.x + threadIdx.x;
    if (i >= N) return;
    float b = beta[i];
    float t = atanhf(b);
    g_q[i] = t * t + 0.01f;
    float4 v0 = *(const float4*)(x + (size_t)i * 8);
    float4 v1 = *(const float4*)(x + (size_t)i * 8 + 4);
    float n2 = v0.x * v0.x + v0.y * v0.y + v0.z * v0.z + v0.w * v0.w
             + v1.x * v1.x + v1.y * v1.y + v1.z * v1.z + v1.w * v1.w;
    g_n2[i] = n2;
    int p = pid[i];
    if (p > 0 && p < NPIDMAX) {
        unsigned long long key =
            ((unsigned long long)__float_as_uint(b) << 32) |
            (unsigned long long)(0xFFFFFFFFu - (unsigned)i);
        atomicMax(&g_best[p], key);
    }
}

__global__ void k_compact() {
    int p = blockIdx.x * blockDim.x + threadIdx.x;
    if (p <= 0 || p >= NPIDMAX) return;
    unsigned long long key = g_best[p];
    if (key != 0ULL) {
        int idx = (int)(0xFFFFFFFFu - (unsigned)(key & 0xFFFFFFFFull));
        int pos = atomicAdd(&g_cpcount, 1);
        g_cplist[pos] = idx;
    }
}

// attraction: sum over masked hits of ||x_i - x_alpha||^2 * q_i * q_alpha
__global__ void k_attract(const float* __restrict__ x, const int* __restrict__ pid,
                          const int* __restrict__ recon, const float* __restrict__ pt,
                          const float* __restrict__ eta, int N) {
    int i = blockIdx.x * blockDim.x + threadIdx.x;
    float va = 0.0f; int m = 0;
    if (i < N) {
        int p = pid[i];
        if (p > 0 && pt[i] > 0.9f && recon[i] > 0 && fabsf(eta[i]) < 4.0f) {
            unsigned long long key = g_best[p];
            int a = (int)(0xFFFFFFFFu - (unsigned)(key & 0xFFFFFFFFull));
            const float4* xi = (const float4*)(x + (size_t)i * 8);
            const float4* xa = (const float4*)(x + (size_t)a * 8);
            float4 i0 = xi[0], i1 = xi[1], a0 = xa[0], a1 = xa[1];
            float d, d2 = 0.0f;
            d = i0.x - a0.x; d2 += d * d;
            d = i0.y - a0.y; d2 += d * d;
            d = i0.z - a0.z; d2 += d * d;
            d = i0.w - a0.w; d2 += d * d;
            d = i1.x - a1.x; d2 += d * d;
            d = i1.y - a1.y; d2 += d * d;
            d = i1.z - a1.z; d2 += d * d;
            d = i1.w - a1.w; d2 += d * d;
            va = d2 * g_q[i] * g_q[a];
            m = 1;
        }
    }
    #pragma unroll
    for (int o = 16; o; o >>= 1) {
        va += __shfl_down_sync(0xFFFFFFFFu, va, o);
        m  += __shfl_down_sync(0xFFFFFFFFu, m,  o);
    }
    if ((threadIdx.x & 31) == 0 && (m || va != 0.0f)) {
        atomicAdd(&g_att, (double)va);
        atomicAdd(&g_maskcnt, m);
    }
}

// ---- repulsion: two-pass histogram top-(K+1) with register-resident CP data ----
__global__ void __launch_bounds__(RT, 2) k_repulse(const float* __restrict__ x,
                                                   const int* __restrict__ pid, int N) {
    __shared__ int      s_hist[CPT][NB];
    __shared__ int      s_Bs[CPT];
    __shared__ int      s_rs[CPT];
    __shared__ int      s_bcnt[CPT];
    __shared__ unsigned s_bk[CPT][BCAP];
    __shared__ float    s_bw[CPT][BCAP];
    __shared__ float    s_red[RT / 32];

    int tid   = threadIdx.x;
    int ncp   = g_cpcount;
    int cbase = blockIdx.x * CPT;
    if (cbase >= ncp) return;

    // register-resident CP data (padded slots never hit radius)
    float xc[CPT][8], n2c[CPT], qc[CPT];
    int   pidc[CPT];
    #pragma unroll
    for (int c = 0; c < CPT; c++) {
        int slot = cbase + c;
        bool act = slot < ncp;
        int ci = act ? g_cplist[slot] : 0;
        n2c[c]  = act ? g_n2[ci] : 1e30f;
        pidc[c] = act ? pid[ci]  : -1;
        qc[c]   = act ? g_q[ci]  : 0.0f;
        #pragma unroll
        for (int d = 0; d < 8; d++) xc[c][d] = act ? x[(size_t)ci * 8 + d] : 0.0f;
    }

    for (int h = tid; h < CPT * NB; h += RT) ((int*)s_hist)[h] = 0;
    if (tid < CPT) s_bcnt[tid] = 0;
    __syncthreads();

    // ---- Pass A: count histogram of d2 (in-radius, self included) ----
    for (int j = tid; j < N; j += RT) {
        float4 v0 = *(const float4*)(x + (size_t)j * 8);
        float4 v1 = *(const float4*)(x + (size_t)j * 8 + 4);
        float n2j = g_n2[j];
        #pragma unroll
        for (int c = 0; c < CPT; c++) {
            float dot = v0.x * xc[c][0];
            dot = fmaf(v0.y, xc[c][1], dot);
            dot = fmaf(v0.z, xc[c][2], dot);
            dot = fmaf(v0.w, xc[c][3], dot);
            dot = fmaf(v1.x, xc[c][4], dot);
            dot = fmaf(v1.y, xc[c][5], dot);
            dot = fmaf(v1.z, xc[c][6], dot);
            dot = fmaf(v1.w, xc[c][7], dot);
            float d2 = fmaf(-2.0f, dot, n2j + n2c[c]);
            if (d2 <= 1.0f) {
                float d2c = fmaxf(d2, 0.0f);
                int b = min((int)(d2c * (float)NB), NB - 1);
                atomicAdd(&s_hist[c][b], 1);
            }
        }
    }
    __syncthreads();

    // ---- selection: boundary bin B and residual r per CP ----
    if (tid < CPT) {
        int cum = 0, B = NB, r = 0;
        for (int b = 0; b < NB; b++) {
            int nc = cum + s_hist[tid][b];
            if (nc >= KSEL2) { B = b; r = KSEL2 - cum; break; }
            cum = nc;
        }
        s_Bs[tid] = B; s_rs[tid] = r;
    }
    __syncthreads();

    int Breg[CPT];
    #pragma unroll
    for (int c = 0; c < CPT; c++) Breg[c] = s_Bs[c];

    // ---- Pass B: accumulate bins < B; gather boundary-bin candidates ----
    float acc[CPT];
    #pragma unroll
    for (int c = 0; c < CPT; c++) acc[c] = 0.0f;

    for (int j = tid; j < N; j += RT) {
        float4 v0 = *(const float4*)(x + (size_t)j * 8);
        float4 v1 = *(const float4*)(x + (size_t)j * 8 + 4);
        float n2j = g_n2[j];
        int   pj  = pid[j];
        float qj  = g_q[j];
        #pragma unroll
        for (int c = 0; c < CPT; c++) {
            float dot = v0.x * xc[c][0];
            dot = fmaf(v0.y, xc[c][1], dot);
            dot = fmaf(v0.z, xc[c][2], dot);
            dot = fmaf(v0.w, xc[c][3], dot);
            dot = fmaf(v1.x, xc[c][4], dot);
            dot = fmaf(v1.y, xc[c][5], dot);
            dot = fmaf(v1.z, xc[c][6], dot);
            dot = fmaf(v1.w, xc[c][7], dot);
            float d2 = fmaf(-2.0f, dot, n2j + n2c[c]);
            if (d2 <= 1.0f) {
                float d2c = fmaxf(d2, 0.0f);
                int b = min((int)(d2c * (float)NB), NB - 1);
                int B = Breg[c];
                if (b < B) {
                    if (pj != pidc[c]) acc[c] += (1.0f - sqrtf(d2c)) * qj;
                } else if (b == B) {
                    float w = (pj != pidc[c]) ? (1.0f - sqrtf(d2c)) * qj : 0.0f;
                    int p = atomicAdd(&s_bcnt[c], 1);
                    if (p < BCAP) { s_bk[c][p] = __float_as_uint(d2c); s_bw[c][p] = w; }
                }
            }
        }
    }
    __syncthreads();

    // ---- boundary mini-rank + per-CP reduction ----
    #pragma unroll
    for (int c = 0; c < CPT; c++) {
        float part = acc[c];
        int m = min(s_bcnt[c], BCAP);
        int r = s_rs[c];
        if (r > 0) {
            for (int e = tid; e < m; e += RT) {
                unsigned ke = s_bk[c][e];
                int rank = 0;
                for (int k = 0; k < m; k++) {
                    unsigned kk = s_bk[c][k];
                    rank += (kk < ke) || (kk == ke && k < e);
                }
                if (rank < r) part += s_bw[c][e];
            }
        }
        #pragma unroll
        for (int o = 16; o; o >>= 1) part += __shfl_down_sync(0xFFFFFFFFu, part, o);
        if ((tid & 31) == 0) s_red[tid >> 5] = part;
        __syncthreads();
        if (tid == 0) {
            float tot = 0.0f;
            #pragma unroll
            for (int w = 0; w < RT / 32; w++) tot += s_red[w];
            if (tot != 0.0f) atomicAdd(&g_rep, (double)(tot * qc[c]));
        }
        __syncthreads();
    }
}

__global__ void k_final(float* out, int N) {
    if (blockIdx.x == 0 && threadIdx.x == 0) {
        int mc = g_maskcnt;
        out[0] = (float)(mc > 0 ? g_att / (double)mc : 0.0);
        out[1] = (float)(g_rep / (double)N);
        out[2] = 0.0f;
        out[3] = 0.0f;
    }
}

extern "C" void kernel_launch(void* const* d_in, const int* in_sizes, int n_in,
                              void* d_out, int out_size) {
    const float* beta  = (const float*)d_in[0];
    const float* x     = (const float*)d_in[1];
    const int*   pid   = (const int*)d_in[2];
    const int*   recon = (const int*)d_in[3];
    const float* pt    = (const float*)d_in[4];
    const float* eta   = (const float*)d_in[5];
    float* out = (float*)d_out;
    int N = in_sizes[0];

    k_init<<<(NPIDMAX + 255) / 256, 256>>>();
    k_bestq<<<(N + 255) / 256, 256>>>(beta, pid, x, N);
    k_compact<<<(NPIDMAX + 255) / 256, 256>>>();
    k_attract<<<(N + 127) / 128, 128>>>(x, pid, recon, pt, eta, N);
    int ngrp = (NPIDMAX + CPT - 1) / CPT;   // 256 blocks; ~250 active
    k_repulse<<<ngrp, RT>>>(x, pid, N);
    k_final<<<1, 32>>>(out, N);
}